// round 11
// baseline (speedup 1.0000x reference)
#include <cuda_runtime.h>

// SU2Attention: batch=1, seq=2048, heads=8, spinor_dim=2 (complex).
// Per head: Q=K are 4-dim real unit vectors u_j = s_j/||s_j||, logits u_i.u_j
// scaled by 1/sqrt(2) (bounded -> no max subtraction), softmax over keys,
// values are raw 4-vectors s_j.
//
// Output layout (verified R5-R10): PLANAR — real plane (2048*8*2 floats) then
// imag plane. d_in[0]=real, d_in[1]=imag.
//
// R11: occupancy via multi-block co-residency. R7-R10 evidence: every config
// sat at 32 warps/SM (1 block/SM, grid 128 < 148 SMs) with issue ~50% and no
// pipe saturated. QTILE=32/BLOCK=512 -> 512 blocks, 3 co-resident per SM
// (74 KB smem each, regs capped 42) = 48 warps/SM.

#define SEQ    2048
#define HEADS  8
#define QTILE  32
#define BLOCK  512
#define NWARP  (BLOCK / 32)         // 16 key-splits
#define JCHUNK (SEQ / NWARP)        // 128 keys per warp

typedef unsigned long long u64_t;

__device__ __forceinline__ float2 fmul2(float2 a, float2 b) {
    float2 d;
    asm("mul.rn.f32x2 %0, %1, %2;"
        : "=l"(reinterpret_cast<u64_t&>(d))
        : "l"(reinterpret_cast<const u64_t&>(a)),
          "l"(reinterpret_cast<const u64_t&>(b)));
    return d;
}

__device__ __forceinline__ float2 ffma2(float2 a, float2 b, float2 c) {
    float2 d;
    asm("fma.rn.f32x2 %0, %1, %2, %3;"
        : "=l"(reinterpret_cast<u64_t&>(d))
        : "l"(reinterpret_cast<const u64_t&>(a)),
          "l"(reinterpret_cast<const u64_t&>(b)),
          "l"(reinterpret_cast<const u64_t&>(c)));
    return d;
}

__device__ __forceinline__ float ex2_approx(float x) {
    float r;
    asm("ex2.approx.ftz.f32 %0, %1;" : "=f"(r) : "f"(x));
    return r;
}

__global__ __launch_bounds__(BLOCK, 3)
void su2_attn_kernel(const float* __restrict__ p0,   // spinors_real
                     const float* __restrict__ p1,   // spinors_imag
                     float* __restrict__ out) {
    // Dynamic shared (74 KB):
    //   su:   SEQ float4 unit vectors      (32 KB)
    //   sv:   SEQ float4 raw vectors       (32 KB)
    //   pacc: NWARP x QTILE float4 partial ( 8 KB)
    //   pden: NWARP x QTILE float  partial ( 2 KB)
    extern __shared__ float4 smem[];
    float4* su   = smem;
    float4* sv   = smem + SEQ;
    float4* pacc = smem + 2 * SEQ;                       // [NWARP][QTILE]
    float*  pden = reinterpret_cast<float*>(pacc + NWARP * QTILE);

    const int h    = blockIdx.y;
    const int q0   = blockIdx.x * QTILE;
    const int lane = threadIdx.x & 31;
    const int warp = threadIdx.x >> 5;

    // Cooperative load + normalize of all SEQ vectors for this head.
    for (int j = threadIdx.x; j < SEQ; j += BLOCK) {
        const int base = (j * HEADS + h) * 2;
        float2 a = *reinterpret_cast<const float2*>(p0 + base);  // real (d0,d1)
        float2 b = *reinterpret_cast<const float2*>(p1 + base);  // imag (d0,d1)
        float x = a.x, y = a.y, z = b.x, w = b.y;
        float n2 = x*x + y*y + z*z + w*w;
        float rn = rsqrtf(n2);
        sv[j] = make_float4(x, y, z, w);
        su[j] = make_float4(x*rn, y*rn, z*rn, w*rn);
    }
    __syncthreads();

    // One query per thread (lane): qi = q0 + lane.
    // Fold SCALE*log2(e) into the query: exp(dot*SCALE) = 2^(dot').
    const float C = 0.70710678118654752f * 1.44269504088896341f;
    const float4 qu = su[q0 + lane];
    const float2 qs01 = make_float2(qu.x * C, qu.y * C);
    const float2 qs23 = make_float2(qu.z * C, qu.w * C);

    float2 acc01 = make_float2(0.f, 0.f);
    float2 acc23 = make_float2(0.f, 0.f);
    float  den = 0.f;

    const int jlo = warp * JCHUNK;
    #pragma unroll 8
    for (int j = jlo; j < jlo + JCHUNK; ++j) {
        float4 u = su[j];                      // LDS.128, warp-broadcast
        float4 v = sv[j];                      // LDS.128, warp-broadcast
        float2 d2 = ffma2(qs23, make_float2(u.z, u.w),
                          fmul2(qs01, make_float2(u.x, u.y)));
        float t = d2.x + d2.y;                 // horizontal add
        float e = ex2_approx(t);               // MUFU.EX2
        float2 e2 = make_float2(e, e);
        acc01 = ffma2(e2, make_float2(v.x, v.y), acc01);
        acc23 = ffma2(e2, make_float2(v.z, v.w), acc23);
        den += e;
    }

    pacc[warp * QTILE + lane] = make_float4(acc01.x, acc01.y, acc23.x, acc23.y);
    pden[warp * QTILE + lane] = den;
    __syncthreads();

    // Stage A: 4 groups of 4 splits -> 4 partials per query (128 threads).
    if (threadIdx.x < 4 * QTILE) {
        const int q = threadIdx.x & (QTILE - 1);
        const int g = threadIdx.x >> 5;              // 0..3
        const int s0 = g * 4;
        float4 a = pacc[s0 * QTILE + q];
        float  d = pden[s0 * QTILE + q];
        #pragma unroll
        for (int s = 1; s < 4; ++s) {
            float4 b = pacc[(s0 + s) * QTILE + q];
            a.x += b.x; a.y += b.y; a.z += b.z; a.w += b.w;
            d += pden[(s0 + s) * QTILE + q];
        }
        pacc[s0 * QTILE + q] = a;
        pden[s0 * QTILE + q] = d;
    }
    __syncthreads();

    // Stage B: 32 threads finish the 4-way sum, normalize, store planar.
    if (threadIdx.x < QTILE) {
        const int q = threadIdx.x;
        float4 a = pacc[q];
        float  d = pden[q];
        #pragma unroll
        for (int g = 1; g < 4; ++g) {
            float4 b = pacc[g * 4 * QTILE + q];
            a.x += b.x; a.y += b.y; a.z += b.z; a.w += b.w;
            d += pden[g * 4 * QTILE + q];
        }
        const float inv = __frcp_rn(d);
        const int ohd = (q0 + q) * HEADS + h;
        // planar complex: real plane then imag plane, each (1,2048,8,2)
        *reinterpret_cast<float2*>(out + ohd * 2) =
            make_float2(a.x * inv, a.y * inv);
        *reinterpret_cast<float2*>(out + SEQ * HEADS * 2 + ohd * 2) =
            make_float2(a.z * inv, a.w * inv);
    }
}

extern "C" void kernel_launch(void* const* d_in, const int* in_sizes, int n_in,
                              void* d_out, int out_size) {
    const float* p0 = (const float*)d_in[0];
    const float* p1 = (const float*)d_in[1];
    float* out = (float*)d_out;

    const int shmem = 2 * SEQ * sizeof(float4)              // su + sv
                    + NWARP * QTILE * sizeof(float4)        // pacc
                    + NWARP * QTILE * sizeof(float);        // pden
    cudaFuncSetAttribute(su2_attn_kernel,
                         cudaFuncAttributeMaxDynamicSharedMemorySize, shmem);

    dim3 grid(SEQ / QTILE, HEADS);                          // 64 x 8 = 512
    dim3 block(BLOCK);
    su2_attn_kernel<<<grid, block, shmem>>>(p0, p1, out);
}

// round 12
// speedup vs baseline: 1.3930x; 1.3930x over previous
#include <cuda_runtime.h>

// SU2Attention: batch=1, seq=2048, heads=8, spinor_dim=2 (complex).
// Per head: Q=K are 4-dim real unit vectors u_j = s_j/||s_j||, logits u_i.u_j
// scaled by 1/sqrt(2) (bounded -> no max subtraction), softmax over keys,
// values are raw 4-vectors s_j.
//
// Output layout (verified R5-R11): PLANAR — real plane (2048*8*2 floats) then
// imag plane. d_in[0]=real, d_in[1]=imag.
//
// R12: R8 config (best: BLOCK=1024, NQ=4 queries/thread, 32 key-splits)
// + explicit 2-stage software pipeline: next key's u/v LDS issued before the
// current key's compute, hiding the 29-cycle LDS latency under the
// dot->EX2->acc chain within the 64-reg budget.

#define SEQ    2048
#define HEADS  8
#define QTILE  128
#define NQ     4
#define BLOCK  1024
#define NWARP  (BLOCK / 32)         // 32 splits
#define JCHUNK (SEQ / NWARP)        // 64 keys per warp

typedef unsigned long long u64_t;

__device__ __forceinline__ float2 fmul2(float2 a, float2 b) {
    float2 d;
    asm("mul.rn.f32x2 %0, %1, %2;"
        : "=l"(reinterpret_cast<u64_t&>(d))
        : "l"(reinterpret_cast<const u64_t&>(a)),
          "l"(reinterpret_cast<const u64_t&>(b)));
    return d;
}

__device__ __forceinline__ float2 ffma2(float2 a, float2 b, float2 c) {
    float2 d;
    asm("fma.rn.f32x2 %0, %1, %2, %3;"
        : "=l"(reinterpret_cast<u64_t&>(d))
        : "l"(reinterpret_cast<const u64_t&>(a)),
          "l"(reinterpret_cast<const u64_t&>(b)),
          "l"(reinterpret_cast<const u64_t&>(c)));
    return d;
}

__device__ __forceinline__ float ex2_approx(float x) {
    float r;
    asm("ex2.approx.ftz.f32 %0, %1;" : "=f"(r) : "f"(x));
    return r;
}

// One key vs 4 queries. qs01/qs23 hold SCALE*log2e-prescaled query comps.
__device__ __forceinline__ void body(const float4& u, const float4& v,
                                     const float2* __restrict__ qs01,
                                     const float2* __restrict__ qs23,
                                     float2* __restrict__ acc01,
                                     float2* __restrict__ acc23,
                                     float* __restrict__ den) {
    float2 u01 = make_float2(u.x, u.y);
    float2 u23 = make_float2(u.z, u.w);
    float2 v01 = make_float2(v.x, v.y);
    float2 v23 = make_float2(v.z, v.w);
    #pragma unroll
    for (int i = 0; i < NQ; ++i) {
        float2 d2 = ffma2(qs23[i], u23, fmul2(qs01[i], u01));
        float t = d2.x + d2.y;                 // horizontal add
        float e = ex2_approx(t);               // MUFU.EX2
        float2 e2 = make_float2(e, e);
        acc01[i] = ffma2(e2, v01, acc01[i]);
        acc23[i] = ffma2(e2, v23, acc23[i]);
        den[i] += e;
    }
}

__global__ __launch_bounds__(BLOCK, 1)
void su2_attn_kernel(const float* __restrict__ p0,   // spinors_real
                     const float* __restrict__ p1,   // spinors_imag
                     float* __restrict__ out) {
    // Dynamic shared (144 KB):
    //   su:   SEQ float4 unit vectors      (32 KB)
    //   sv:   SEQ float4 raw vectors       (32 KB)
    //   pacc: NWARP x QTILE float4 partial (64 KB)
    //   pden: NWARP x QTILE float  partial (16 KB)
    extern __shared__ float4 smem[];
    float4* su   = smem;
    float4* sv   = smem + SEQ;
    float4* pacc = smem + 2 * SEQ;                       // [NWARP][QTILE]
    float*  pden = reinterpret_cast<float*>(pacc + NWARP * QTILE);

    const int h    = blockIdx.y;
    const int q0   = blockIdx.x * QTILE;
    const int lane = threadIdx.x & 31;
    const int warp = threadIdx.x >> 5;

    // Cooperative load + normalize of all SEQ vectors for this head.
    for (int j = threadIdx.x; j < SEQ; j += BLOCK) {
        const int base = (j * HEADS + h) * 2;
        float2 a = *reinterpret_cast<const float2*>(p0 + base);  // real (d0,d1)
        float2 b = *reinterpret_cast<const float2*>(p1 + base);  // imag (d0,d1)
        float x = a.x, y = a.y, z = b.x, w = b.y;
        float n2 = x*x + y*y + z*z + w*w;
        float rn = rsqrtf(n2);
        sv[j] = make_float4(x, y, z, w);
        su[j] = make_float4(x*rn, y*rn, z*rn, w*rn);
    }
    __syncthreads();

    // Each thread owns NQ queries: q = q0 + lane + 32*i.
    // Fold SCALE*log2(e) into the queries: exp(dot*SCALE) = 2^(dot').
    const float C = 0.70710678118654752f * 1.44269504088896341f;
    float2 qs01[NQ], qs23[NQ];
    #pragma unroll
    for (int i = 0; i < NQ; ++i) {
        float4 qu = su[q0 + lane + 32 * i];
        qs01[i] = make_float2(qu.x * C, qu.y * C);
        qs23[i] = make_float2(qu.z * C, qu.w * C);
    }

    float2 acc01[NQ], acc23[NQ];
    float  den[NQ];
    #pragma unroll
    for (int i = 0; i < NQ; ++i) {
        acc01[i] = make_float2(0.f, 0.f);
        acc23[i] = make_float2(0.f, 0.f);
        den[i] = 0.f;
    }

    const int jlo = warp * JCHUNK;

    // 2-stage software pipeline: LDS for key j+1 issued before compute of j.
    float4 u = su[jlo];
    float4 v = sv[jlo];
    #pragma unroll 8
    for (int j = jlo; j < jlo + JCHUNK - 1; ++j) {
        float4 un = su[j + 1];                 // prefetch next key
        float4 vn = sv[j + 1];
        body(u, v, qs01, qs23, acc01, acc23, den);
        u = un;
        v = vn;
    }
    body(u, v, qs01, qs23, acc01, acc23, den); // epilogue: last key

    // Write per-warp partials.
    #pragma unroll
    for (int i = 0; i < NQ; ++i) {
        const int q = lane + 32 * i;
        pacc[warp * QTILE + q] = make_float4(acc01[i].x, acc01[i].y,
                                             acc23[i].x, acc23[i].y);
        pden[warp * QTILE + q] = den[i];
    }
    __syncthreads();

    // Stage A: 8 groups of 4 splits -> 8 partials per query.
    {
        const int q = threadIdx.x & (QTILE - 1);
        const int g = threadIdx.x >> 7;              // 0..7
        const int s0 = g * 4;
        float4 a = pacc[s0 * QTILE + q];
        float  d = pden[s0 * QTILE + q];
        #pragma unroll
        for (int s = 1; s < 4; ++s) {
            float4 b = pacc[(s0 + s) * QTILE + q];
            a.x += b.x; a.y += b.y; a.z += b.z; a.w += b.w;
            d += pden[(s0 + s) * QTILE + q];
        }
        __syncthreads();
        pacc[s0 * QTILE + q] = a;
        pden[s0 * QTILE + q] = d;
    }
    __syncthreads();

    // Stage B: 128 threads finish the 8-way sum, normalize, store planar.
    if (threadIdx.x < QTILE) {
        const int q = threadIdx.x;
        float4 a = pacc[q];
        float  d = pden[q];
        #pragma unroll
        for (int g = 1; g < 8; ++g) {
            float4 b = pacc[g * 4 * QTILE + q];
            a.x += b.x; a.y += b.y; a.z += b.z; a.w += b.w;
            d += pden[g * 4 * QTILE + q];
        }
        const float inv = __frcp_rn(d);
        const int ohd = (q0 + q) * HEADS + h;
        // planar complex: real plane then imag plane, each (1,2048,8,2)
        *reinterpret_cast<float2*>(out + ohd * 2) =
            make_float2(a.x * inv, a.y * inv);
        *reinterpret_cast<float2*>(out + SEQ * HEADS * 2 + ohd * 2) =
            make_float2(a.z * inv, a.w * inv);
    }
}

extern "C" void kernel_launch(void* const* d_in, const int* in_sizes, int n_in,
                              void* d_out, int out_size) {
    const float* p0 = (const float*)d_in[0];
    const float* p1 = (const float*)d_in[1];
    float* out = (float*)d_out;

    const int shmem = 2 * SEQ * sizeof(float4)              // su + sv
                    + NWARP * QTILE * sizeof(float4)        // pacc
                    + NWARP * QTILE * sizeof(float);        // pden
    cudaFuncSetAttribute(su2_attn_kernel,
                         cudaFuncAttributeMaxDynamicSharedMemorySize, shmem);

    dim3 grid(SEQ / QTILE, HEADS);
    dim3 block(BLOCK);
    su2_attn_kernel<<<grid, block, shmem>>>(p0, p1, out);
}